// round 7
// baseline (speedup 1.0000x reference)
#include <cuda_runtime.h>
#include <math.h>

#ifndef M_PI
#define M_PI 3.14159265358979323846
#endif

namespace {

constexpr int NP = 6;
constexpr int NWARP = 8;
constexpr int NTHR = NWARP * 32;

typedef unsigned long long u64;

// pair index tables packed as nibbles: entry t at bits [4t,4t+4)
__device__ constexpr u64 CI_PACK = 0x0433222111100000ull;
__device__ constexpr u64 CJ_PACK = 0x0554543543254321ull;

// rank-3 factor of F_ud: F_ud = sum_c g_L[c] g_L[c]^T
__device__ float g_L[3][64];

// MLP weights in constant memory (separate constant/uniform port, not L1TEX)
__constant__ __align__(16) float c_W1[4 * 32];
__constant__ __align__(16) float c_b1[32];
__constant__ __align__(16) float c_W2[32 * 32];
__constant__ __align__(16) float c_b2[32];
__constant__ __align__(16) float c_W3[32];
__constant__ float c_misc[2];  // [0]=b3, [1]=scale

struct __align__(16) Smem {
  float4 F4[2][32][32];          // [m][k2][l] = (F[2k2][l],F[2k2][l+32],F[2k2+1][l],F[2k2+1][l+32])
  float2 phis2[NWARP][NP][64];   // duplicated: phis2[..][k] = (phi_k, phi_k)
  float  red[NWARP][32 * 33];    // transpose-reduction scratch: row v (stride 33), col lane
  float  fin[NWARP][16];         // final A entries for pfaffian
  float  xs[NWARP][NP][2];
};

__device__ __forceinline__ u64 pk2(float a, float b) {
  u64 r; asm("mov.b64 %0, {%1, %2};" : "=l"(r) : "f"(a), "f"(b)); return r;
}
__device__ __forceinline__ void upk2(float& a, float& b, u64 v) {
  asm("mov.b64 {%0, %1}, %2;" : "=f"(a), "=f"(b) : "l"(v));
}
__device__ __forceinline__ void fma2(u64& d, u64 a, u64 b) {
  asm("fma.rn.f32x2 %0, %1, %2, %3;" : "=l"(d) : "l"(a), "l"(b), "l"(d));
}
__device__ __forceinline__ float hdot2(u64 a, u64 b) {
  u64 p; asm("mul.rn.f32x2 %0, %1, %2;" : "=l"(p) : "l"(a), "l"(b));
  float lo, hi; upk2(lo, hi, p);
  return lo + hi;
}
__device__ __forceinline__ float silu_f(float x) {
  float t;
  asm("tanh.approx.f32 %0, %1;" : "=f"(t) : "f"(x * 0.5f));
  return 0.5f * x * (1.0f + t);
}
__device__ __forceinline__ u64 ldc64(const float* p) {
  return *reinterpret_cast<const u64*>(p);
}

// ---------- pre-kernel: pivoted rank-3 Cholesky of F_ud ----------
__global__ void factor_kernel(const float* __restrict__ F_ud) {
  __shared__ float diag[64];
  __shared__ float Lc[3][64];
  __shared__ int pivs;
  const int tid = threadIdx.x;  // 64 threads
  diag[tid] = F_ud[tid * 64 + tid];
  __syncthreads();
  for (int r = 0; r < 3; r++) {
    if (tid == 0) {
      int p = 0; float best = diag[0];
      for (int q = 1; q < 64; q++) if (diag[q] > best) { best = diag[q]; p = q; }
      pivs = p;
    }
    __syncthreads();
    const int p = pivs;
    float dp = diag[p];
    float col = F_ud[tid * 64 + p];
    for (int rp = 0; rp < r; rp++) col -= Lc[rp][tid] * Lc[rp][p];
    float inv = (dp > 1e-20f) ? (float)(1.0 / sqrt((double)dp)) : 0.f;
    float Lv = col * inv;
    __syncthreads();
    Lc[r][tid] = Lv;
    diag[tid] -= Lv * Lv;
    __syncthreads();
  }
  for (int r = 0; r < 3; r++) g_L[r][tid] = Lc[r][tid];
}

// ---------- main kernel ----------
__global__ void __launch_bounds__(NTHR, 2)
pfaffian_kernel(const float* __restrict__ x, const int* __restrict__ spin,
                const float* __restrict__ F_uu, const float* __restrict__ F_dd,
                float* __restrict__ out, int Bt) {
  extern __shared__ char smem_raw[];
  Smem* S = reinterpret_cast<Smem*>(smem_raw);
  const int tid = threadIdx.x;
  const int w = tid >> 5, lane = tid & 31;

  // ---- stage antisymmetrized F_uu / F_dd (pair-packed) ----
  for (int idx = tid; idx < 2 * 32 * 32; idx += NTHR) {
    int m = idx >> 10, r = idx & 1023, k2 = r >> 5, l = r & 31;
    int k = 2 * k2;
    const float* F = m ? F_dd : F_uu;
    float4 v;
    v.x = F[k * 64 + l]            - F[l * 64 + k];
    v.y = F[k * 64 + l + 32]       - F[(l + 32) * 64 + k];
    v.z = F[(k + 1) * 64 + l]      - F[l * 64 + k + 1];
    v.w = F[(k + 1) * 64 + l + 32] - F[(l + 32) * 64 + k + 1];
    S->F4[m][k2][l] = v;
  }
  __syncthreads();

  // ---- per-lane basis norm constants ----
  const int nx1 = lane >> 3, nyi = lane & 7;
  float nA = 0.f, nB = 0.f, nC = 0.f;
  {
    double spi = sqrt(M_PI);
    double d = 1.0;
    for (int m2 = 0; m2 < 8; m2++) {
      float v = (float)(1.0 / sqrt(d * spi));
      if (m2 == nx1) nA = v;
      if (m2 == nx1 + 4) nB = v;
      if (m2 == nyi) nC = v;
      d *= 2.0 * (m2 + 1);
    }
  }
  const float norm1 = nA * nC, norm2 = nB * nC;
  const float b3v = c_misc[0], scl = c_misc[1];

  // rank-3 factor columns for this lane's two basis cols
  u64 Lpk[3];
#pragma unroll
  for (int c = 0; c < 3; c++) Lpk[c] = pk2(g_L[c][lane], g_L[c][lane + 32]);

  // per-lane pair tables (t = lane & 15; slot 15 dummy = (0,1))
  const int tID = lane & 15;
  const int pi_t = (int)((CI_PACK >> (4 * tID)) & 15);
  const int pj_t = (int)((CJ_PACK >> (4 * tID)) & 15);

  const int ngroups = (Bt + NWARP - 1) / NWARP;
  for (int g = blockIdx.x; g < ngroups; g += gridDim.x) {
    const int e = g * NWARP + w;
    if (e >= Bt) continue;

    // ---- load x, spin ----
    int sval = 0;
    if (lane < NP) {
      float2 xv = *reinterpret_cast<const float2*>(x + (size_t)e * NP * 2 + lane * 2);
      S->xs[w][lane][0] = xv.x;
      S->xs[w][lane][1] = xv.y;
      sval = spin[(size_t)e * NP + lane];
    }
    unsigned mask = __ballot_sync(0xffffffffu, (lane < NP) && (sval == 1));
    __syncwarp();

    // ---- basis Phi ----
    float phiA[NP], phiB[NP];
#pragma unroll
    for (int p = 0; p < NP; p++) {
      float u = S->xs[w][p][0], v = S->xs[w][p][1];
      float hm = 1.f, h = 2.f * u;
      float hxa = (nx1 == 0) ? 1.f : h;
      float hxb = h;
#pragma unroll
      for (int k = 2; k < 8; k++) {
        float hn = fmaf(2.f * u, h, -2.f * (float)(k - 1) * hm);
        hm = h; h = hn;
        if (nx1 == k) hxa = hn;
        if (nx1 + 4 == k) hxb = hn;
      }
      float gm = 1.f, gh = 2.f * v;
      float hy = (nyi == 0) ? 1.f : gh;
#pragma unroll
      for (int k = 2; k < 8; k++) {
        float gn = fmaf(2.f * v, gh, -2.f * (float)(k - 1) * gm);
        gm = gh; gh = gn;
        if (nyi == k) hy = gn;
      }
      float gexp = __expf(-0.5f * (u * u + v * v));
      phiA[p] = hxa * hy * (norm1 * gexp);
      phiB[p] = hxb * hy * (norm2 * gexp);
      S->phis2[w][p][lane]      = make_float2(phiA[p], phiA[p]);
      S->phis2[w][p][lane + 32] = make_float2(phiB[p], phiB[p]);
    }
    __syncwarp();

    // ---- k-loop: uu + dd GEMVs, packed f32x2 ----
    u64 acc_uu[NP], acc_dd[NP];
#pragma unroll
    for (int p = 0; p < NP; p++) { acc_uu[p] = 0ull; acc_dd[p] = 0ull; }

#pragma unroll 8
    for (int k2 = 0; k2 < 32; k2++) {
      ulonglong2 fu = *reinterpret_cast<const ulonglong2*>(&S->F4[0][k2][lane]);
      ulonglong2 fd = *reinterpret_cast<const ulonglong2*>(&S->F4[1][k2][lane]);
#pragma unroll
      for (int p = 0; p < NP; p++) {
        ulonglong2 pv = *reinterpret_cast<const ulonglong2*>(&S->phis2[w][p][2 * k2]);
        fma2(acc_uu[p], pv.x, fu.x); fma2(acc_uu[p], pv.y, fu.y);
        fma2(acc_dd[p], pv.x, fd.x); fma2(acc_dd[p], pv.y, fd.y);
      }
    }

    // G_same select + packed phi
    u64 Gs[NP], phip[NP];
#pragma unroll
    for (int p = 0; p < NP; p++) {
      Gs[p] = ((mask >> p) & 1) ? acc_dd[p] : acc_uu[p];
      phip[p] = pk2(phiA[p], phiB[p]);
    }

    // ---- transpose reduction of 32 partials (15 ds + t[0..16]); t17 via butterfly ----
    {
      constexpr int PIc[15] = {0,0,0,0,0,1,1,1,1,2,2,2,3,3,4};
      constexpr int PJc[15] = {1,2,3,4,5,2,3,4,5,3,4,5,4,5,5};
#pragma unroll
      for (int t = 0; t < 15; t++)
        S->red[w][t * 33 + lane] = hdot2(Gs[PIc[t]], phip[PJc[t]]);
#pragma unroll
      for (int p = 0; p < NP; p++)
#pragma unroll
        for (int c = 0; c < 3; c++) {
          int ti = p * 3 + c;
          if (ti < 17) S->red[w][(15 + ti) * 33 + lane] = hdot2(phip[p], Lpk[c]);
        }
    }
    float t17 = hdot2(phip[5], Lpk[2]);
#pragma unroll
    for (int off = 16; off; off >>= 1)
      t17 += __shfl_xor_sync(0xffffffffu, t17, off);
    __syncwarp();

    // each lane sums one value's 32 partials (conflict-free: bank = (lane+s)&31)
    float tot;
    {
      float s0 = 0.f, s1 = 0.f, s2 = 0.f, s3 = 0.f;
      const float* row = &S->red[w][lane * 33];
#pragma unroll
      for (int s = 0; s < 32; s += 4) {
        s0 += row[s]; s1 += row[s + 1]; s2 += row[s + 2]; s3 += row[s + 3];
      }
      tot = (s0 + s1) + (s2 + s3);
    }

    // ---- gather t-values for this lane's pair; compute abase ----
    float abase;
    {
      const int i = pi_t, j = pj_t;
      float fv = 0.f;
#pragma unroll
      for (int c = 0; c < 3; c++) {
        int ia = 3 * i + c, ib = 3 * j + c;
        int sa = (ia >= 17) ? 0 : (15 + ia);
        int sb = (ib >= 17) ? 0 : (15 + ib);
        float va = __shfl_sync(0xffffffffu, tot, sa);
        float vb = __shfl_sync(0xffffffffu, tot, sb);
        va = (ia == 17) ? t17 : va;
        vb = (ib == 17) ? t17 : vb;
        fv = fmaf(va, vb, fv);
      }
      int si = (mask >> i) & 1, sj = (mask >> j) & 1;
      abase = (si == sj) ? tot : ((si == 0) ? fv : -fv);
    }

    // ---- pair-correction MLP (packed f32x2, weights in constant memory) ----
    float finalA = 0.f;
    {
      bool rev = lane >= 16;
      int i = rev ? pj_t : pi_t;
      int j = rev ? pi_t : pj_t;
      float f0 = S->xs[w][i][0] - S->xs[w][j][0];
      float f1 = S->xs[w][i][1] - S->xs[w][j][1];
      float f2v = f0 * f0 + f1 * f1;
      float f3 = (((mask >> i) & 1) == ((mask >> j) & 1)) ? 1.f : 0.f;

      u64 d0 = pk2(f0, f0), d1 = pk2(f1, f1), d2 = pk2(f2v, f2v), d3 = pk2(f3, f3);

      // layer 1: 32 neurons as 16 packed pairs
      float h1r[32];
#pragma unroll
      for (int o2 = 0; o2 < 16; o2++) {
        u64 acc = ldc64(&c_b1[2 * o2]);
        fma2(acc, d0, ldc64(&c_W1[0 * 32 + 2 * o2]));
        fma2(acc, d1, ldc64(&c_W1[1 * 32 + 2 * o2]));
        fma2(acc, d2, ldc64(&c_W1[2 * 32 + 2 * o2]));
        fma2(acc, d3, ldc64(&c_W1[3 * 32 + 2 * o2]));
        float s0, s1; upk2(s0, s1, acc);
        h1r[2 * o2] = silu_f(s0);
        h1r[2 * o2 + 1] = silu_f(s1);
      }

      // layer 2: 32x32 packed, k outer
      u64 acc2[16];
#pragma unroll
      for (int o2 = 0; o2 < 16; o2++)
        acc2[o2] = ldc64(&c_b2[2 * o2]);
#pragma unroll 8
      for (int k = 0; k < 32; k++) {
        u64 hk = pk2(h1r[k], h1r[k]);
#pragma unroll
        for (int q = 0; q < 16; q++) {
          fma2(acc2[q], hk, ldc64(&c_W2[k * 32 + 2 * q]));
        }
      }

      // layer 3
      u64 oacc = 0ull;
#pragma unroll
      for (int o2 = 0; o2 < 16; o2++) {
        float s0, s1; upk2(s0, s1, acc2[o2]);
        u64 sp = pk2(silu_f(s0), silu_f(s1));
        fma2(oacc, sp, ldc64(&c_W3[2 * o2]));
      }
      float o0, o1; upk2(o0, o1, oacc);
      float outv = b3v + o0 + o1;

      float orev = __shfl_down_sync(0xffffffffu, outv, 16);
      finalA = abase + scl * (outv - orev);  // valid on lanes 0..14
    }

    // ---- stash A entries; lane 0 computes Pfaffian ----
    if (lane < 15) S->fin[w][lane] = finalA;
    __syncwarp();
    if (lane == 0) {
      float4 q0 = *reinterpret_cast<const float4*>(&S->fin[w][0]);
      float4 q1 = *reinterpret_cast<const float4*>(&S->fin[w][4]);
      float4 q2 = *reinterpret_cast<const float4*>(&S->fin[w][8]);
      float4 q3 = *reinterpret_cast<const float4*>(&S->fin[w][12]);
      float a0 = q0.x, a1 = q0.y, a2 = q0.z, a3 = q0.w;
      float a4 = q1.x, a5 = q1.y, a6 = q1.z, a7 = q1.w;
      float a8 = q2.x, a9 = q2.y, a10 = q2.z, a11 = q2.w;
      float a12 = q3.x, a13 = q3.y, a14 = q3.z;
      float pf = a0 * (a9 * a14 - a10 * a13 + a11 * a12)
               - a1 * (a6 * a14 - a7 * a13 + a8 * a12)
               + a2 * (a5 * a14 - a7 * a11 + a8 * a10)
               - a3 * (a5 * a13 - a6 * a11 + a8 * a9)
               + a4 * (a5 * a12 - a6 * a10 + a7 * a9);
      float sgn = (pf == 0.f) ? 1.f : ((pf > 0.f) ? 1.f : -1.f);
      float la = 0.5f * __logf(pf * pf);
      out[e] = sgn;
      out[Bt + e] = la;
    }
    __syncwarp();
  }
}

}  // namespace

extern "C" void kernel_launch(void* const* d_in, const int* in_sizes, int n_in,
                              void* d_out, int out_size) {
  const float* x     = (const float*)d_in[0];
  const int*   spin  = (const int*)d_in[1];
  const float* F_ud  = (const float*)d_in[2];
  const float* F_uu  = (const float*)d_in[3];
  const float* F_dd  = (const float*)d_in[4];
  const float* W1    = (const float*)d_in[5];
  const float* b1    = (const float*)d_in[6];
  const float* W2    = (const float*)d_in[7];
  const float* b2    = (const float*)d_in[8];
  const float* W3    = (const float*)d_in[9];
  const float* b3    = (const float*)d_in[10];
  const float* scale = (const float*)d_in[11];
  float* out = (float*)d_out;

  const int Bt = in_sizes[0] / (NP * 2);
  const int smem = (int)sizeof(Smem);

  // stage MLP weights into constant memory (D2D async on default stream,
  // same capture surface as the kernel launches below)
  cudaMemcpyToSymbolAsync(c_W1, W1, 4 * 32 * sizeof(float), 0, cudaMemcpyDeviceToDevice);
  cudaMemcpyToSymbolAsync(c_b1, b1, 32 * sizeof(float), 0, cudaMemcpyDeviceToDevice);
  cudaMemcpyToSymbolAsync(c_W2, W2, 32 * 32 * sizeof(float), 0, cudaMemcpyDeviceToDevice);
  cudaMemcpyToSymbolAsync(c_b2, b2, 32 * sizeof(float), 0, cudaMemcpyDeviceToDevice);
  cudaMemcpyToSymbolAsync(c_W3, W3, 32 * sizeof(float), 0, cudaMemcpyDeviceToDevice);
  cudaMemcpyToSymbolAsync(c_misc, b3, sizeof(float), 0, cudaMemcpyDeviceToDevice);
  cudaMemcpyToSymbolAsync(c_misc, scale, sizeof(float), sizeof(float), cudaMemcpyDeviceToDevice);

  // rank-3 factorization of F_ud
  factor_kernel<<<1, 64>>>(F_ud);

  cudaFuncSetAttribute(pfaffian_kernel, cudaFuncAttributeMaxDynamicSharedMemorySize, smem);

  int dev = 0;
  cudaGetDevice(&dev);
  int nsm = 148;
  cudaDeviceGetAttribute(&nsm, cudaDevAttrMultiProcessorCount, dev);

  const int ngroups = (Bt + NWARP - 1) / NWARP;
  int grid = nsm * 2;
  if (grid > ngroups) grid = ngroups;

  pfaffian_kernel<<<grid, NTHR, smem>>>(x, spin, F_uu, F_dd, out, Bt);
}

// round 8
// speedup vs baseline: 1.5179x; 1.5179x over previous
#include <cuda_runtime.h>
#include <math.h>

#ifndef M_PI
#define M_PI 3.14159265358979323846
#endif

namespace {

constexpr int NP = 6;
constexpr int NWARP = 8;
constexpr int NTHR = NWARP * 32;

typedef unsigned long long u64;

// pair index tables packed as nibbles: entry t at bits [4t,4t+4)
__device__ constexpr u64 CI_PACK = 0x0433222111100000ull;
__device__ constexpr u64 CJ_PACK = 0x0554543543254321ull;

// rank-3 factor of F_ud: F_ud = sum_c g_L[c] g_L[c]^T
__device__ float g_L[3][64];

struct __align__(16) Smem {
  float4 F4[2][32][32];            // 32 KB: [m][k2][l]=(F[2k2][l],F[2k2][l+32],F[2k2+1][l],F[2k2+1][l+32])
  float  phi[NWARP][2][NP][64];    // 24 KB: scalar phi, [warp][elem][particle][k]
  float  red[NWARP][33 * 32];      // 33 KB: transpose-reduction, slot v at [v*33 + lane]
  float  W2s[32 * 32];             // 4 KB, row-major [k][o]
  float  W1s[4 * 32];              // row-major [in][o]
  float  b1s[32], b2s[32], W3ss[32];
  float  xs[NWARP][2][NP][2];
  float  fin[NWARP][2][16];
  float  b3s, scale_s;
};

__device__ __forceinline__ u64 pk2(float a, float b) {
  u64 r; asm("mov.b64 %0, {%1, %2};" : "=l"(r) : "f"(a), "f"(b)); return r;
}
__device__ __forceinline__ void upk2(float& a, float& b, u64 v) {
  asm("mov.b64 {%0, %1}, %2;" : "=f"(a), "=f"(b) : "l"(v));
}
__device__ __forceinline__ void fma2(u64& d, u64 a, u64 b) {
  asm("fma.rn.f32x2 %0, %1, %2, %3;" : "=l"(d) : "l"(a), "l"(b), "l"(d));
}
__device__ __forceinline__ float hdot2(u64 a, u64 b) {
  u64 p; asm("mul.rn.f32x2 %0, %1, %2;" : "=l"(p) : "l"(a), "l"(b));
  float lo, hi; upk2(lo, hi, p);
  return lo + hi;
}
__device__ __forceinline__ float silu_f(float x) {
  float t;
  asm("tanh.approx.f32 %0, %1;" : "=f"(t) : "f"(x * 0.5f));
  return 0.5f * x * (1.0f + t);
}
__device__ __forceinline__ u64 lds64(const float* p) {
  return *reinterpret_cast<const u64*>(p);
}

// ---------- pre-kernel: pivoted rank-3 Cholesky of F_ud ----------
__global__ void factor_kernel(const float* __restrict__ F_ud) {
  __shared__ float diag[64];
  __shared__ float Lc[3][64];
  __shared__ int pivs;
  const int tid = threadIdx.x;  // 64 threads
  diag[tid] = F_ud[tid * 64 + tid];
  __syncthreads();
  for (int r = 0; r < 3; r++) {
    if (tid == 0) {
      int p = 0; float best = diag[0];
      for (int q = 1; q < 64; q++) if (diag[q] > best) { best = diag[q]; p = q; }
      pivs = p;
    }
    __syncthreads();
    const int p = pivs;
    float dp = diag[p];
    float col = F_ud[tid * 64 + p];
    for (int rp = 0; rp < r; rp++) col -= Lc[rp][tid] * Lc[rp][p];
    float inv = (dp > 1e-20f) ? (float)(1.0 / sqrt((double)dp)) : 0.f;
    float Lv = col * inv;
    __syncthreads();
    Lc[r][tid] = Lv;
    diag[tid] -= Lv * Lv;
    __syncthreads();
  }
  for (int r = 0; r < 3; r++) g_L[r][tid] = Lc[r][tid];
}

// ---------- main kernel ----------
__global__ void __launch_bounds__(NTHR, 2)
pfaffian_kernel(const float* __restrict__ x, const int* __restrict__ spin,
                const float* __restrict__ F_uu, const float* __restrict__ F_dd,
                const float* __restrict__ W1, const float* __restrict__ b1,
                const float* __restrict__ W2, const float* __restrict__ b2,
                const float* __restrict__ W3, const float* __restrict__ b3,
                const float* __restrict__ scale,
                float* __restrict__ out, int Bt) {
  extern __shared__ char smem_raw[];
  Smem* S = reinterpret_cast<Smem*>(smem_raw);
  const int tid = threadIdx.x;
  const int w = tid >> 5, lane = tid & 31;

  // ---- stage antisymmetrized F_uu / F_dd (pair-packed) ----
  for (int idx = tid; idx < 2 * 32 * 32; idx += NTHR) {
    int m = idx >> 10, r = idx & 1023, k2 = r >> 5, l = r & 31;
    int k = 2 * k2;
    const float* F = m ? F_dd : F_uu;
    float4 v;
    v.x = F[k * 64 + l]            - F[l * 64 + k];
    v.y = F[k * 64 + l + 32]       - F[(l + 32) * 64 + k];
    v.z = F[(k + 1) * 64 + l]      - F[l * 64 + k + 1];
    v.w = F[(k + 1) * 64 + l + 32] - F[(l + 32) * 64 + k + 1];
    S->F4[m][k2][l] = v;
  }
  // ---- stage MLP weights verbatim (row-major) ----
  for (int idx = tid; idx < 128; idx += NTHR) S->W1s[idx] = W1[idx];
  for (int idx = tid; idx < 1024; idx += NTHR) S->W2s[idx] = W2[idx];
  if (tid < 32) {
    S->b1s[tid] = b1[tid];
    S->b2s[tid] = b2[tid];
    S->W3ss[tid] = W3[tid];
  }
  if (tid == 0) { S->b3s = b3[0]; S->scale_s = scale[0]; }
  __syncthreads();

  // ---- per-lane basis norm constants ----
  const int nx1 = lane >> 3, nyi = lane & 7;
  float nA = 0.f, nB = 0.f, nC = 0.f;
  {
    double spi = sqrt(M_PI);
    double d = 1.0;
    for (int m2 = 0; m2 < 8; m2++) {
      float v = (float)(1.0 / sqrt(d * spi));
      if (m2 == nx1) nA = v;
      if (m2 == nx1 + 4) nB = v;
      if (m2 == nyi) nC = v;
      d *= 2.0 * (m2 + 1);
    }
  }
  const float norm1 = nA * nC, norm2 = nB * nC;
  const float b3v = S->b3s, scl = S->scale_s;

  // rank-3 factor columns for this lane's two basis cols
  u64 Lpk[3];
#pragma unroll
  for (int c = 0; c < 3; c++) Lpk[c] = pk2(g_L[c][lane], g_L[c][lane + 32]);

  // per-lane pair indices (t = lane & 15; slot 15 dummy = (0,1))
  const int tID = lane & 15;
  const int pi_t = (int)((CI_PACK >> (4 * tID)) & 15);
  const int pj_t = (int)((CJ_PACK >> (4 * tID)) & 15);

  const int ngroups = (Bt + 2 * NWARP - 1) / (2 * NWARP);
  for (int g = blockIdx.x; g < ngroups; g += gridDim.x) {
    const int e0 = (g * NWARP + w) * 2;
    const int e1 = e0 + 1;

    // ---- load x, spin for both elements ----
    unsigned mask0, mask1;
    {
      int s0 = 0, s1 = 0;
      if (lane < NP) {
        int ea = (e0 < Bt) ? e0 : 0;
        int eb = (e1 < Bt) ? e1 : 0;
        float2 xv0 = *reinterpret_cast<const float2*>(x + (size_t)ea * NP * 2 + lane * 2);
        float2 xv1 = *reinterpret_cast<const float2*>(x + (size_t)eb * NP * 2 + lane * 2);
        S->xs[w][0][lane][0] = xv0.x; S->xs[w][0][lane][1] = xv0.y;
        S->xs[w][1][lane][0] = xv1.x; S->xs[w][1][lane][1] = xv1.y;
        s0 = spin[(size_t)ea * NP + lane];
        s1 = spin[(size_t)eb * NP + lane];
      }
      mask0 = __ballot_sync(0xffffffffu, (lane < NP) && (s0 == 1));
      mask1 = __ballot_sync(0xffffffffu, (lane < NP) && (s1 == 1));
    }
    __syncwarp();

    // ---- basis Phi for both elements (scalar into smem) ----
    for (int el = 0; el < 2; el++) {
#pragma unroll
      for (int p = 0; p < NP; p++) {
        float u = S->xs[w][el][p][0], v = S->xs[w][el][p][1];
        float hm = 1.f, h = 2.f * u;
        float hxa = (nx1 == 0) ? 1.f : h;
        float hxb = h;
#pragma unroll
        for (int k = 2; k < 8; k++) {
          float hn = fmaf(2.f * u, h, -2.f * (float)(k - 1) * hm);
          hm = h; h = hn;
          if (nx1 == k) hxa = hn;
          if (nx1 + 4 == k) hxb = hn;
        }
        float gm = 1.f, gh = 2.f * v;
        float hy = (nyi == 0) ? 1.f : gh;
#pragma unroll
        for (int k = 2; k < 8; k++) {
          float gn = fmaf(2.f * v, gh, -2.f * (float)(k - 1) * gm);
          gm = gh; gh = gn;
          if (nyi == k) hy = gn;
        }
        float gexp = __expf(-0.5f * (u * u + v * v));
        S->phi[w][el][p][lane]      = hxa * hy * (norm1 * gexp);
        S->phi[w][el][p][lane + 32] = hxb * hy * (norm2 * gexp);
      }
    }
    __syncwarp();

    // ---- shared k-loop: one F read feeds BOTH elements ----
    u64 auu[2][NP], add[2][NP];
#pragma unroll
    for (int el = 0; el < 2; el++)
#pragma unroll
      for (int p = 0; p < NP; p++) { auu[el][p] = 0ull; add[el][p] = 0ull; }

#pragma unroll 2
    for (int kk = 0; kk < 16; kk++) {
      ulonglong2 fu0 = *reinterpret_cast<const ulonglong2*>(&S->F4[0][2 * kk][lane]);
      ulonglong2 fu1 = *reinterpret_cast<const ulonglong2*>(&S->F4[0][2 * kk + 1][lane]);
      ulonglong2 fd0 = *reinterpret_cast<const ulonglong2*>(&S->F4[1][2 * kk][lane]);
      ulonglong2 fd1 = *reinterpret_cast<const ulonglong2*>(&S->F4[1][2 * kk + 1][lane]);
#pragma unroll
      for (int el = 0; el < 2; el++) {
#pragma unroll
        for (int p = 0; p < NP; p++) {
          float4 pv = *reinterpret_cast<const float4*>(&S->phi[w][el][p][4 * kk]);
          u64 q0 = pk2(pv.x, pv.x), q1 = pk2(pv.y, pv.y);
          u64 q2 = pk2(pv.z, pv.z), q3 = pk2(pv.w, pv.w);
          fma2(auu[el][p], q0, fu0.x); fma2(auu[el][p], q1, fu0.y);
          fma2(auu[el][p], q2, fu1.x); fma2(auu[el][p], q3, fu1.y);
          fma2(add[el][p], q0, fd0.x); fma2(add[el][p], q1, fd0.y);
          fma2(add[el][p], q2, fd1.x); fma2(add[el][p], q3, fd1.y);
        }
      }
    }

    // ---- reductions for both elements (consumes accumulators) ----
    float abase[2];
#pragma unroll
    for (int el = 0; el < 2; el++) {
      const unsigned mask = el ? mask1 : mask0;
      u64 phip[NP], Gs[NP];
#pragma unroll
      for (int p = 0; p < NP; p++) {
        phip[p] = pk2(S->phi[w][el][p][lane], S->phi[w][el][p][lane + 32]);
        Gs[p] = ((mask >> p) & 1) ? add[el][p] : auu[el][p];
      }
      {
        constexpr int PIc[15] = {0,0,0,0,0,1,1,1,1,2,2,2,3,3,4};
        constexpr int PJc[15] = {1,2,3,4,5,2,3,4,5,3,4,5,4,5,5};
#pragma unroll
        for (int t = 0; t < 15; t++)
          S->red[w][t * 33 + lane] = hdot2(Gs[PIc[t]], phip[PJc[t]]);
#pragma unroll
        for (int p = 0; p < NP; p++)
#pragma unroll
          for (int c = 0; c < 3; c++) {
            int ti = p * 3 + c;
            if (ti < 17) S->red[w][(15 + ti) * 33 + lane] = hdot2(phip[p], Lpk[c]);
          }
      }
      float t17 = hdot2(phip[5], Lpk[2]);
#pragma unroll
      for (int off = 16; off; off >>= 1)
        t17 += __shfl_xor_sync(0xffffffffu, t17, off);
      __syncwarp();

      // each lane sums one slot's 32 partials (conflict-free rotation)
      float tot;
      {
        float s0 = 0.f, s1 = 0.f, s2 = 0.f, s3 = 0.f;
        const float* row = &S->red[w][lane * 33];
#pragma unroll
        for (int s = 0; s < 32; s += 4) {
          s0 += row[s]; s1 += row[s + 1]; s2 += row[s + 2]; s3 += row[s + 3];
        }
        tot = (s0 + s1) + (s2 + s3);
      }
      __syncwarp();  // red free for next element

      // gather rank-3 t-values for this lane's pair
      float fv = 0.f;
#pragma unroll
      for (int c = 0; c < 3; c++) {
        int ia = 3 * pi_t + c, ib = 3 * pj_t + c;
        int sa = (ia >= 17) ? 0 : (15 + ia);
        int sb = (ib >= 17) ? 0 : (15 + ib);
        float va = __shfl_sync(0xffffffffu, tot, sa);
        float vb = __shfl_sync(0xffffffffu, tot, sb);
        va = (ia == 17) ? t17 : va;
        vb = (ib == 17) ? t17 : vb;
        fv = fmaf(va, vb, fv);
      }
      int si = (mask >> pi_t) & 1, sj = (mask >> pj_t) & 1;
      abase[el] = (si == sj) ? tot : ((si == 0) ? fv : -fv);
    }

    // ---- pair-correction MLP, interleaved over both elements ----
    float final0, final1;
    {
      const bool rev = lane >= 16;
      const int i = rev ? pj_t : pi_t;
      const int j = rev ? pi_t : pj_t;

      float f0a = S->xs[w][0][i][0] - S->xs[w][0][j][0];
      float f1a = S->xs[w][0][i][1] - S->xs[w][0][j][1];
      float f2a = f0a * f0a + f1a * f1a;
      float f3a = (((mask0 >> i) & 1) == ((mask0 >> j) & 1)) ? 1.f : 0.f;
      float f0b = S->xs[w][1][i][0] - S->xs[w][1][j][0];
      float f1b = S->xs[w][1][i][1] - S->xs[w][1][j][1];
      float f2b = f0b * f0b + f1b * f1b;
      float f3b = (((mask1 >> i) & 1) == (((mask1 >> j) & 1))) ? 1.f : 0.f;

      u64 da0 = pk2(f0a, f0a), da1 = pk2(f1a, f1a), da2 = pk2(f2a, f2a), da3 = pk2(f3a, f3a);
      u64 db0 = pk2(f0b, f0b), db1 = pk2(f1b, f1b), db2 = pk2(f2b, f2b), db3 = pk2(f3b, f3b);

      // layer 1: weight loads shared by both elements
      float h1a[32], h1b[32];
#pragma unroll
      for (int o2 = 0; o2 < 16; o2++) {
        u64 bb = lds64(&S->b1s[2 * o2]);
        u64 w0 = lds64(&S->W1s[0 * 32 + 2 * o2]);
        u64 w1_ = lds64(&S->W1s[1 * 32 + 2 * o2]);
        u64 w2_ = lds64(&S->W1s[2 * 32 + 2 * o2]);
        u64 w3_ = lds64(&S->W1s[3 * 32 + 2 * o2]);
        u64 aa = bb, ab = bb;
        fma2(aa, da0, w0); fma2(aa, da1, w1_); fma2(aa, da2, w2_); fma2(aa, da3, w3_);
        fma2(ab, db0, w0); fma2(ab, db1, w1_); fma2(ab, db2, w2_); fma2(ab, db3, w3_);
        float s0, s1; upk2(s0, s1, aa);
        h1a[2 * o2] = silu_f(s0); h1a[2 * o2 + 1] = silu_f(s1);
        upk2(s0, s1, ab);
        h1b[2 * o2] = silu_f(s0); h1b[2 * o2 + 1] = silu_f(s1);
      }

      // layer 2 + 3: process output neurons in quarters of 8; weights shared
      u64 oacc_a = 0ull, oacc_b = 0ull;
#pragma unroll
      for (int q = 0; q < 4; q++) {
        u64 aca[4], acb[4];
#pragma unroll
        for (int o2 = 0; o2 < 4; o2++) {
          u64 bb = lds64(&S->b2s[8 * q + 2 * o2]);
          aca[o2] = bb; acb[o2] = bb;
        }
#pragma unroll 8
        for (int k = 0; k < 32; k++) {
          ulonglong2 wv = *reinterpret_cast<const ulonglong2*>(&S->W2s[k * 32 + 8 * q]);
          ulonglong2 wv2 = *reinterpret_cast<const ulonglong2*>(&S->W2s[k * 32 + 8 * q + 4]);
          u64 hka = pk2(h1a[k], h1a[k]);
          u64 hkb = pk2(h1b[k], h1b[k]);
          fma2(aca[0], hka, wv.x);  fma2(aca[1], hka, wv.y);
          fma2(aca[2], hka, wv2.x); fma2(aca[3], hka, wv2.y);
          fma2(acb[0], hkb, wv.x);  fma2(acb[1], hkb, wv.y);
          fma2(acb[2], hkb, wv2.x); fma2(acb[3], hkb, wv2.y);
        }
#pragma unroll
        for (int o2 = 0; o2 < 4; o2++) {
          u64 w3v = lds64(&S->W3ss[8 * q + 2 * o2]);
          float s0, s1; upk2(s0, s1, aca[o2]);
          u64 spa = pk2(silu_f(s0), silu_f(s1));
          fma2(oacc_a, spa, w3v);
          upk2(s0, s1, acb[o2]);
          u64 spb = pk2(silu_f(s0), silu_f(s1));
          fma2(oacc_b, spb, w3v);
        }
      }
      float oa0, oa1, ob0, ob1;
      upk2(oa0, oa1, oacc_a);
      upk2(ob0, ob1, oacc_b);
      float outa = b3v + oa0 + oa1;
      float outb = b3v + ob0 + ob1;

      float reva = __shfl_down_sync(0xffffffffu, outa, 16);
      float revb = __shfl_down_sync(0xffffffffu, outb, 16);
      final0 = abase[0] + scl * (outa - reva);  // valid on lanes 0..14
      final1 = abase[1] + scl * (outb - revb);
    }

    // ---- stash A entries; lane 0 computes both Pfaffians ----
    if (lane < 15) {
      S->fin[w][0][lane] = final0;
      S->fin[w][1][lane] = final1;
    }
    __syncwarp();
    if (lane == 0) {
#pragma unroll
      for (int el = 0; el < 2; el++) {
        const int e = el ? e1 : e0;
        if (e < Bt) {
          float4 q0 = *reinterpret_cast<const float4*>(&S->fin[w][el][0]);
          float4 q1 = *reinterpret_cast<const float4*>(&S->fin[w][el][4]);
          float4 q2 = *reinterpret_cast<const float4*>(&S->fin[w][el][8]);
          float4 q3 = *reinterpret_cast<const float4*>(&S->fin[w][el][12]);
          float a0 = q0.x, a1 = q0.y, a2 = q0.z, a3 = q0.w;
          float a4 = q1.x, a5 = q1.y, a6 = q1.z, a7 = q1.w;
          float a8 = q2.x, a9 = q2.y, a10 = q2.z, a11 = q2.w;
          float a12 = q3.x, a13 = q3.y, a14 = q3.z;
          float pf = a0 * (a9 * a14 - a10 * a13 + a11 * a12)
                   - a1 * (a6 * a14 - a7 * a13 + a8 * a12)
                   + a2 * (a5 * a14 - a7 * a11 + a8 * a10)
                   - a3 * (a5 * a13 - a6 * a11 + a8 * a9)
                   + a4 * (a5 * a12 - a6 * a10 + a7 * a9);
          float sgn = (pf == 0.f) ? 1.f : ((pf > 0.f) ? 1.f : -1.f);
          float la = 0.5f * __logf(pf * pf);
          out[e] = sgn;
          out[Bt + e] = la;
        }
      }
    }
    __syncwarp();
  }
}

}  // namespace

extern "C" void kernel_launch(void* const* d_in, const int* in_sizes, int n_in,
                              void* d_out, int out_size) {
  const float* x     = (const float*)d_in[0];
  const int*   spin  = (const int*)d_in[1];
  const float* F_ud  = (const float*)d_in[2];
  const float* F_uu  = (const float*)d_in[3];
  const float* F_dd  = (const float*)d_in[4];
  const float* W1    = (const float*)d_in[5];
  const float* b1    = (const float*)d_in[6];
  const float* W2    = (const float*)d_in[7];
  const float* b2    = (const float*)d_in[8];
  const float* W3    = (const float*)d_in[9];
  const float* b3    = (const float*)d_in[10];
  const float* scale = (const float*)d_in[11];
  float* out = (float*)d_out;

  const int Bt = in_sizes[0] / (NP * 2);
  const int smem = (int)sizeof(Smem);

  // rank-3 factorization of F_ud
  factor_kernel<<<1, 64>>>(F_ud);

  cudaFuncSetAttribute(pfaffian_kernel, cudaFuncAttributeMaxDynamicSharedMemorySize, smem);

  int dev = 0;
  cudaGetDevice(&dev);
  int nsm = 148;
  cudaDeviceGetAttribute(&nsm, cudaDevAttrMultiProcessorCount, dev);

  const int ngroups = (Bt + 2 * NWARP - 1) / (2 * NWARP);
  int grid = nsm * 2;
  if (grid > ngroups) grid = ngroups;

  pfaffian_kernel<<<grid, NTHR, smem>>>(x, spin, F_uu, F_dd,
                                        W1, b1, W2, b2, W3, b3, scale, out, Bt);
}